// round 13
// baseline (speedup 1.0000x reference)
#include <cuda_runtime.h>

#define CH_L   4096
#define CH_T   128
#define NEG_INF (-1e30f)
#define LOG2E  1.4426950408889634f

typedef unsigned long long u64;

struct M2 { float a00, a01, a10, a11; };  // max-plus 2x2 operator (log2 domain)

__device__ __forceinline__ void step_vec(float& m0, float& m1, float c, float a) {
    float x0 = m0 - c;
    float x1 = m1 + c;
    m0 = fmaxf(x0 + a, x1 - a);
    m1 = fmaxf(x0 - a, x1 + a);
}
__device__ __forceinline__ void step_mat(M2& M, float c, float a) {
    step_vec(M.a00, M.a10, c, a);
    step_vec(M.a01, M.a11, c, a);
}
// C = A ∘ B (B applied first)
__device__ __forceinline__ M2 compose(const M2& A, const M2& B) {
    M2 C;
    C.a00 = fmaxf(A.a00 + B.a00, A.a01 + B.a10);
    C.a01 = fmaxf(A.a00 + B.a01, A.a01 + B.a11);
    C.a10 = fmaxf(A.a10 + B.a00, A.a11 + B.a10);
    C.a11 = fmaxf(A.a10 + B.a01, A.a11 + B.a11);
    return C;
}
__device__ __forceinline__ M2 m2_identity() { return M2{0.f, NEG_INF, NEG_INF, 0.f}; }

// v = M · (0,0)
__device__ __forceinline__ void apply0(const M2& M, float& v0, float& v1) {
    v0 = fmaxf(M.a00, M.a01);
    v1 = fmaxf(M.a10, M.a11);
}
// v = M · v
__device__ __forceinline__ void applyv(const M2& M, float& v0, float& v1) {
    float r0 = fmaxf(M.a00 + v0, M.a01 + v1);
    float r1 = fmaxf(M.a10 + v0, M.a11 + v1);
    v0 = r0; v1 = r1;
}

// ---- packed f32x2 helpers ----
__device__ __forceinline__ u64 pk2(float lo, float hi) {
    u64 r; asm("mov.b64 %0, {%1,%2};" : "=l"(r) : "f"(lo), "f"(hi)); return r;
}
__device__ __forceinline__ void upk2(float& lo, float& hi, u64 v) {
    asm("mov.b64 {%0,%1}, %2;" : "=f"(lo), "=f"(hi) : "l"(v));
}
__device__ __forceinline__ u64 fadd2(u64 a, u64 b) {
    u64 r; asm("add.rn.f32x2 %0, %1, %2;" : "=l"(r) : "l"(a), "l"(b)); return r;
}
__device__ __forceinline__ float ex2(float x) {
    float r; asm("ex2.approx.f32 %0, %1;" : "=f"(r) : "f"(x)); return r;
}
__device__ __forceinline__ u64 step2(u64 m, u64 dc, u64 aa, u64 na) {
    u64 x = fadd2(m, dc);
    u64 p = fadd2(x, aa), q = fadd2(x, na);
    float pl, ph, ql, qh; upk2(pl, ph, p); upk2(ql, qh, q);
    return pk2(fmaxf(pl, qh), fmaxf(ql, ph));
}

__device__ __forceinline__ M2 ld4(float4 v) { return M2{v.x, v.y, v.z, v.w}; }

__device__ __forceinline__ M2 shfl_up_m2(M2 m, int d) {
    M2 r;
    r.a00 = __shfl_up_sync(0xffffffffu, m.a00, d);
    r.a01 = __shfl_up_sync(0xffffffffu, m.a01, d);
    r.a10 = __shfl_up_sync(0xffffffffu, m.a10, d);
    r.a11 = __shfl_up_sync(0xffffffffu, m.a11, d);
    return r;
}
__device__ __forceinline__ M2 shfl_dn_m2(M2 m, int d) {
    M2 r;
    r.a00 = __shfl_down_sync(0xffffffffu, m.a00, d);
    r.a01 = __shfl_down_sync(0xffffffffu, m.a01, d);
    r.a10 = __shfl_down_sync(0xffffffffu, m.a10, d);
    r.a11 = __shfl_down_sync(0xffffffffu, m.a11, d);
    return r;
}

__global__ __launch_bounds__(CH_T, 8)
void chain_bp_kernel(const float* __restrict__ jp,
                     const float* __restrict__ bp,
                     const int*   __restrict__ obs,
                     float*       __restrict__ out,
                     int nrows) {
    __shared__ float4 s_tab[256];        // 8-step operator table (4 KB)
    __shared__ float4 s_wtF[4];
    __shared__ float4 s_wtB[4];

    const int tid  = threadIdx.x;
    const int lane = tid & 31;
    const int wp   = tid >> 5;

    const float a  = 0.25f * jp[0] * LOG2E;
    const float c0 = 0.5f  * bp[0] * LOG2E;
    const float c1 = 0.5f  * bp[1] * LOG2E;

    // ---- 0. per-block table build (amortized over ~3.5 rows) ----
    #pragma unroll
    for (int e = 0; e < 2; e++) {
        int x = tid + e * CH_T;
        M2 M = m2_identity();
        #pragma unroll
        for (int k = 0; k < 8; k++) {
            float c = ((x >> k) & 1) ? c1 : c0;
            step_mat(M, c, a);
        }
        s_tab[x] = make_float4(M.a00, M.a01, M.a10, M.a11);
    }
    __syncthreads();

    // ---- packed constants ----
    const u64 dc0p = pk2(-c0,  c0);
    const u64 dc1p = pk2(-c1,  c1);
    const u64 aa   = pk2( a,   a);
    const u64 na   = pk2(-a,  -a);

    const int wbase = wp << 10;

    for (int row = blockIdx.x; row < nrows; row += gridDim.x) {

        // ---- 1. obs ingest, warp-local: lane k keeps ballot word k ----
        unsigned int w = 0;
        const int* orow = obs + (size_t)row * CH_L;
        #pragma unroll
        for (int i = 0; i < 32; i++) {
            int o = orow[wbase + (i << 5) + lane];
            unsigned int bal = __ballot_sync(0xffffffffu, o != 0);
            if (i == lane) w = bal;
        }

        // ---- 2. segment operators + partials (seeds derived below) ----
        M2 tb0 = ld4(s_tab[ w        & 255u]);
        M2 tb1 = ld4(s_tab[(w >>  8) & 255u]);
        M2 tb2 = ld4(s_tab[(w >> 16) & 255u]);
        M2 tb3 = ld4(s_tab[(w >> 24) & 255u]);
        M2 P2 = compose(tb1, tb0);                 // fwd op for bits 0..15
        M2 F  = compose(tb3, compose(tb2, P2));

        M2 uB0 = ld4(s_tab[__brev( w        & 255u) >> 24]);
        M2 uB1 = ld4(s_tab[__brev((w >>  8) & 255u) >> 24]);
        M2 uB2 = ld4(s_tab[__brev((w >> 16) & 255u) >> 24]);
        M2 uB3 = ld4(s_tab[__brev((w >> 24) & 255u) >> 24]);
        M2 U23 = compose(uB2, uB3);                // bwd op for pos 16..31
        M2 Bm  = compose(uB0, compose(uB1, U23));

        // ---- 3. merged warp scans: fwd prefix + bwd suffix ----
        M2 curF = F, curB = Bm;
        #pragma unroll
        for (int off = 1; off < 32; off <<= 1) {
            M2 lF = shfl_up_m2(curF, off);
            M2 rB = shfl_dn_m2(curB, off);
            if (lane >= off)      curF = compose(curF, lF);
            if (lane + off < 32)  curB = compose(curB, rB);
        }
        if (lane == 31) s_wtF[wp] = make_float4(curF.a00, curF.a01, curF.a10, curF.a11);
        if (lane == 0)  s_wtB[wp] = make_float4(curB.a00, curB.a01, curB.a10, curB.a11);
        __syncthreads();

        // ---- 4. cross-warp carries (vector form) ----
        float fc0 = 0.f, fc1 = 0.f;
        if (wp >= 1) { M2 T = ld4(s_wtF[0]); apply0(T, fc0, fc1); }
        if (wp >= 2) { M2 T = ld4(s_wtF[1]); applyv(T, fc0, fc1); }
        if (wp >= 3) { M2 T = ld4(s_wtF[2]); applyv(T, fc0, fc1); }
        float gc0 = 0.f, gc1 = 0.f;
        if (wp <= 2) { M2 T = ld4(s_wtB[3]); apply0(T, gc0, gc1); }
        if (wp <= 1) { M2 T = ld4(s_wtB[2]); applyv(T, gc0, gc1); }
        if (wp == 0) { M2 T = ld4(s_wtB[1]); applyv(T, gc0, gc1); }

        // within-warp boundary messages
        M2 sp = shfl_up_m2(curF, 1);
        float f0 = fc0, f1 = fc1;               // fwd msg at segment pos 0
        if (lane > 0) applyv(sp, f0, f1);
        M2 sn = shfl_dn_m2(curB, 1);
        float g0 = gc0, g1 = gc1;               // bwd msg at segment pos 31
        if (lane < 31) applyv(sn, g0, g1);

        // ---- 5. all chain seeds upfront (table matrices die here) ----
        // fwd seeds: pos 0 / 8 / 16 / 24
        float sA0l = f0, sA0h = f1;
        float sB0l = f0, sB0h = f1; applyv(tb0, sB0l, sB0h);
        float sA1l = f0, sA1h = f1; applyv(P2,  sA1l, sA1h);
        float sB1l = sA1l, sB1h = sA1h; applyv(tb2, sB1l, sB1h);
        // bwd seeds: pos 31 / 23 / 15 / 7
        float bB1l = g0, bB1h = g1;
        float bA1l = g0, bA1h = g1; applyv(uB3, bA1l, bA1h);
        float bB0l = g0, bB0h = g1; applyv(U23, bB0l, bB0h);
        float bA0l = bB0l, bA0h = bB0h; applyv(uB1, bA0l, bA0h);

        float4* o0 = (float4*)(out + (size_t)row * 2 * CH_L);
        float4* o1 = o0 + (CH_L / 4);
        const int gbase = tid * 8;       // my 8 global float4 slots per state

        // ---- 6. two 16-position chunks: register x-buffer + direct STG ----
        #pragma unroll
        for (int h = 0; h < 2; h++) {
            const int kb = h << 4;               // chunk bit base

            // -- fwd replay: 2 interleaved 8-step chains -> register buffer --
            u64 mA = h ? pk2(sA1l, sA1h) : pk2(sA0l, sA0h);
            u64 mB = h ? pk2(sB1l, sB1h) : pk2(sB0l, sB0h);
            float4 x0[4], x1[4];                 // [j]: A:j=0,1  B:j=2,3
            #pragma unroll
            for (int k4 = 0; k4 < 2; k4++) {
                float4 vA0, vA1, vB0, vB1;
                #pragma unroll
                for (int c = 0; c < 4; c++) {
                    const int kA = kb + k4 * 4 + c;
                    const int kB = kA + 8;
                    u64 dcA = ((w >> kA) & 1u) ? dc1p : dc0p;
                    u64 dcB = ((w >> kB) & 1u) ? dc1p : dc0p;
                    u64 xA = fadd2(mA, dcA);
                    u64 xB = fadd2(mB, dcB);
                    float al, ah, bl, bh; upk2(al, ah, xA); upk2(bl, bh, xB);
                    if (c == 0)      { vA0.x = al; vA1.x = ah; vB0.x = bl; vB1.x = bh; }
                    else if (c == 1) { vA0.y = al; vA1.y = ah; vB0.y = bl; vB1.y = bh; }
                    else if (c == 2) { vA0.z = al; vA1.z = ah; vB0.z = bl; vB1.z = bh; }
                    else             { vA0.w = al; vA1.w = ah; vB0.w = bl; vB1.w = bh; }
                    if (!(k4 == 1 && c == 3)) {
                        u64 pA = fadd2(xA, aa), qA = fadd2(xA, na);
                        u64 pB = fadd2(xB, aa), qB = fadd2(xB, na);
                        float p0,p1,q0,q1;
                        upk2(p0,p1,pA); upk2(q0,q1,qA); mA = pk2(fmaxf(p0,q1), fmaxf(q0,p1));
                        upk2(p0,p1,pB); upk2(q0,q1,qB); mB = pk2(fmaxf(p0,q1), fmaxf(q0,p1));
                    }
                }
                x0[k4]     = vA0;  x1[k4]     = vA1;
                x0[2 + k4] = vB0;  x1[2 + k4] = vB1;
            }

            // -- bwd replay: combine in-register, exp2, direct STG.128 --
            u64 nA = h ? pk2(bA1l, bA1h) : pk2(bA0l, bA0h);  // bwd at local pos 7
            u64 nB = h ? pk2(bB1l, bB1h) : pk2(bB0l, bB0h);  // bwd at local pos 15
            #pragma unroll
            for (int k4 = 1; k4 >= 0; k4--) {
                float4 nA0, nA1, nB0, nB1;
                #pragma unroll
                for (int c = 3; c >= 0; c--) {
                    const int p = k4 * 4 + c;             // chain-local pos 7..0
                    float al, ah, bl, bh; upk2(al, ah, nA); upk2(bl, bh, nB);
                    if (c == 0)      { nA0.x = al; nA1.x = ah; nB0.x = bl; nB1.x = bh; }
                    else if (c == 1) { nA0.y = al; nA1.y = ah; nB0.y = bl; nB1.y = bh; }
                    else if (c == 2) { nA0.z = al; nA1.z = ah; nB0.z = bl; nB1.z = bh; }
                    else             { nA0.w = al; nA1.w = ah; nB0.w = bl; nB1.w = bh; }
                    if (p > 0) {
                        u64 dcA = ((w >> (kb + p))     & 1u) ? dc1p : dc0p;
                        u64 dcB = ((w >> (kb + 8 + p)) & 1u) ? dc1p : dc0p;
                        nA = step2(nA, dcA, aa, na);
                        nB = step2(nB, dcB, aa, na);
                    }
                }
                // chain A -> global float4 idx gbase + h*4 + k4
                {
                    float4 fv0 = x0[k4], fv1 = x1[k4];
                    u64 s0a = fadd2(pk2(fv0.x, fv0.y), pk2(nA0.x, nA0.y));
                    u64 s0b = fadd2(pk2(fv0.z, fv0.w), pk2(nA0.z, nA0.w));
                    u64 s1a = fadd2(pk2(fv1.x, fv1.y), pk2(nA1.x, nA1.y));
                    u64 s1b = fadd2(pk2(fv1.z, fv1.w), pk2(nA1.z, nA1.w));
                    float4 o0v, o1v; float lo, hi;
                    upk2(lo, hi, s0a); o0v.x = ex2(lo); o0v.y = ex2(hi);
                    upk2(lo, hi, s0b); o0v.z = ex2(lo); o0v.w = ex2(hi);
                    upk2(lo, hi, s1a); o1v.x = ex2(lo); o1v.y = ex2(hi);
                    upk2(lo, hi, s1b); o1v.z = ex2(lo); o1v.w = ex2(hi);
                    o0[gbase + (h << 2) + k4] = o0v;
                    o1[gbase + (h << 2) + k4] = o1v;
                }
                // chain B -> global float4 idx gbase + h*4 + 2 + k4
                {
                    float4 fv0 = x0[2 + k4], fv1 = x1[2 + k4];
                    u64 s0a = fadd2(pk2(fv0.x, fv0.y), pk2(nB0.x, nB0.y));
                    u64 s0b = fadd2(pk2(fv0.z, fv0.w), pk2(nB0.z, nB0.w));
                    u64 s1a = fadd2(pk2(fv1.x, fv1.y), pk2(nB1.x, nB1.y));
                    u64 s1b = fadd2(pk2(fv1.z, fv1.w), pk2(nB1.z, nB1.w));
                    float4 o0v, o1v; float lo, hi;
                    upk2(lo, hi, s0a); o0v.x = ex2(lo); o0v.y = ex2(hi);
                    upk2(lo, hi, s0b); o0v.z = ex2(lo); o0v.w = ex2(hi);
                    upk2(lo, hi, s1a); o1v.x = ex2(lo); o1v.y = ex2(hi);
                    upk2(lo, hi, s1b); o1v.z = ex2(lo); o1v.w = ex2(hi);
                    o0[gbase + (h << 2) + 2 + k4] = o0v;
                    o1[gbase + (h << 2) + 2 + k4] = o1v;
                }
            }
        }
        __syncthreads();   // protect s_wtF/s_wtB before next row's scan writes
    }
}

extern "C" void kernel_launch(void* const* d_in, const int* in_sizes, int n_in,
                              void* d_out, int out_size) {
    const float* jp  = (const float*)d_in[0];
    const float* bp  = (const float*)d_in[1];
    const int*   obs = (const int*)  d_in[2];
    float*       out = (float*)d_out;

    int B = in_sizes[2] / CH_L;
    int grid = 148 * 8;
    if (grid > B) grid = B;
    chain_bp_kernel<<<grid, CH_T>>>(jp, bp, obs, out, B);
}

// round 16
// speedup vs baseline: 1.1341x; 1.1341x over previous
#include <cuda_runtime.h>

#define CH_L   4096
#define CH_T   128     // threads per block
#define CH_SEG 32      // CH_L / CH_T
#define NEG_INF (-1e30f)
#define LOG2E  1.4426950408889634f

struct M2 { float a00, a01, a10, a11; };  // max-plus 2x2 operator (log2 domain)

// one BP step in log2 domain: m' = T_c(m)
__device__ __forceinline__ void step_vec(float& m0, float& m1, float c, float a) {
    float x0 = m0 - c;
    float x1 = m1 + c;
    m0 = fmaxf(x0 + a, x1 - a);
    m1 = fmaxf(x0 - a, x1 + a);
}
__device__ __forceinline__ void step_mat(M2& M, float c, float a) {
    step_vec(M.a00, M.a10, c, a);
    step_vec(M.a01, M.a11, c, a);
}
// C = A ∘ B (B applied first)
__device__ __forceinline__ M2 compose(const M2& A, const M2& B) {
    M2 C;
    C.a00 = fmaxf(A.a00 + B.a00, A.a01 + B.a10);
    C.a01 = fmaxf(A.a00 + B.a01, A.a01 + B.a11);
    C.a10 = fmaxf(A.a10 + B.a00, A.a11 + B.a10);
    C.a11 = fmaxf(A.a10 + B.a01, A.a11 + B.a11);
    return C;
}
__device__ __forceinline__ M2 m2_identity() { return M2{0.f, NEG_INF, NEG_INF, 0.f}; }

__device__ __forceinline__ float ex2(float x) {
    float r; asm("ex2.approx.f32 %0, %1;" : "=f"(r) : "f"(x)); return r;
}

// bank-conflict-free swizzle for the [L] belief arrays:
// replay writes (t = i*32+k across threads i) and epilogue reads (t consecutive)
// both hit distinct banks.
__device__ __forceinline__ int swz(int t) {
    return (t & ~31) | ((t + (t >> 5)) & 31);
}

__global__ __launch_bounds__(CH_T)
void chain_bp_kernel(const float* __restrict__ jp,
                     const float* __restrict__ bp,
                     const int*   __restrict__ obs,
                     float*       __restrict__ out,
                     int nrows) {
    __shared__ float4 s_tab[256];          // 8-step operator table (log2 domain)
    __shared__ unsigned int sbits[CH_T];   // 1 bit per position
    __shared__ float sb0[CH_L];            // log2-belief state 0 (swizzled)
    __shared__ float sb1[CH_L];            // log2-belief state 1 (swizzled)
    __shared__ float sm0[CH_T], sm1[CH_T], sm2[CH_T], sm3[CH_T];  // scan (SoA)

    const int tid = threadIdx.x;

    const float a  = 0.25f * jp[0] * LOG2E;
    const float c0 = 0.5f  * bp[0] * LOG2E;
    const float c1 = 0.5f  * bp[1] * LOG2E;

    // ---- 0. per-block table build (amortized over ~5.5 rows) ----
    #pragma unroll
    for (int e = 0; e < 2; e++) {
        int x = tid + e * CH_T;
        M2 M = m2_identity();
        #pragma unroll
        for (int k = 0; k < 8; k++) {
            float c = ((x >> k) & 1) ? c1 : c0;
            step_mat(M, c, a);
        }
        s_tab[x] = make_float4(M.a00, M.a01, M.a10, M.a11);
    }
    __syncthreads();

    for (int row = blockIdx.x; row < nrows; row += gridDim.x) {

        // ---- 1. coalesced obs load -> 1-bit mask per position via ballot ----
        const int* orow = obs + (size_t)row * CH_L;
        #pragma unroll
        for (int t = tid; t < CH_L; t += CH_T) {
            int o = orow[t];
            unsigned int bal = __ballot_sync(0xffffffffu, o != 0);
            if ((tid & 31) == 0) sbits[t >> 5] = bal;
        }
        __syncthreads();

        const unsigned int w = sbits[tid];     // my 32 positions' bits
        const int base = tid * CH_SEG;

        // ---- 2. forward segment operator from smem table ----
        float4 v0t = s_tab[ w        & 255u];
        float4 v1t = s_tab[(w >>  8) & 255u];
        float4 v2t = s_tab[(w >> 16) & 255u];
        float4 v3t = s_tab[(w >> 24) & 255u];
        M2 tb0 = M2{v0t.x, v0t.y, v0t.z, v0t.w};
        M2 tb1 = M2{v1t.x, v1t.y, v1t.z, v1t.w};
        M2 tb2 = M2{v2t.x, v2t.y, v2t.z, v2t.w};
        M2 tb3 = M2{v3t.x, v3t.y, v3t.z, v3t.w};
        M2 F = compose(tb3, compose(tb2, compose(tb1, tb0)));

        // ---- 3. Kogge-Stone inclusive PREFIX scan of F ----
        M2 cur = F;
        sm0[tid] = cur.a00; sm1[tid] = cur.a01; sm2[tid] = cur.a10; sm3[tid] = cur.a11;
        #pragma unroll
        for (int off = 1; off < CH_T; off <<= 1) {
            __syncthreads();
            M2 left;
            bool act = (tid >= off);
            if (act) {
                left.a00 = sm0[tid - off]; left.a01 = sm1[tid - off];
                left.a10 = sm2[tid - off]; left.a11 = sm3[tid - off];
            }
            __syncthreads();
            if (act) {
                cur = compose(cur, left);
                sm0[tid] = cur.a00; sm1[tid] = cur.a01; sm2[tid] = cur.a10; sm3[tid] = cur.a11;
            }
        }
        __syncthreads();
        float f0 = 0.f, f1 = 0.f;
        if (tid > 0) {
            f0 = fmaxf(sm0[tid - 1], sm1[tid - 1]);
            f1 = fmaxf(sm2[tid - 1], sm3[tid - 1]);
        }
        __syncthreads();   // done reading prefix results; smem reused for suffix

        // ---- 4. backward segment operator (bit-reversed byte lookups) ----
        float4 r0t = s_tab[__brev( w        & 255u) >> 24];
        float4 r1t = s_tab[__brev((w >>  8) & 255u) >> 24];
        float4 r2t = s_tab[__brev((w >> 16) & 255u) >> 24];
        float4 r3t = s_tab[__brev((w >> 24) & 255u) >> 24];
        M2 uB0 = M2{r0t.x, r0t.y, r0t.z, r0t.w};
        M2 uB1 = M2{r1t.x, r1t.y, r1t.z, r1t.w};
        M2 uB2 = M2{r2t.x, r2t.y, r2t.z, r2t.w};
        M2 uB3 = M2{r3t.x, r3t.y, r3t.z, r3t.w};
        M2 Bm = compose(uB0, compose(uB1, compose(uB2, uB3)));

        // ---- 5. Kogge-Stone inclusive SUFFIX scan of B ----
        cur = Bm;
        sm0[tid] = cur.a00; sm1[tid] = cur.a01; sm2[tid] = cur.a10; sm3[tid] = cur.a11;
        #pragma unroll
        for (int off = 1; off < CH_T; off <<= 1) {
            __syncthreads();
            M2 right;
            bool act = (tid + off < CH_T);
            if (act) {
                right.a00 = sm0[tid + off]; right.a01 = sm1[tid + off];
                right.a10 = sm2[tid + off]; right.a11 = sm3[tid + off];
            }
            __syncthreads();
            if (act) {
                cur = compose(cur, right);
                sm0[tid] = cur.a00; sm1[tid] = cur.a01; sm2[tid] = cur.a10; sm3[tid] = cur.a11;
            }
        }
        __syncthreads();
        float g0 = 0.f, g1 = 0.f;   // bwd msg at segment end (pos base+31)
        if (tid < CH_T - 1) {
            g0 = fmaxf(sm0[tid + 1], sm1[tid + 1]);
            g1 = fmaxf(sm2[tid + 1], sm3[tid + 1]);
        }

        // ---- 6. forward replay: write lphi + lfwd into shared ----
        float m0 = f0, m1 = f1;
        #pragma unroll
        for (int k = 0; k < CH_SEG; k++) {
            float c = ((w >> k) & 1u) ? c1 : c0;
            int idx = swz(base + k);
            sb0[idx] = m0 - c;          // x[t][0] = lphi + lfwd
            sb1[idx] = m1 + c;
            step_vec(m0, m1, c, a);
        }

        // ---- 7. backward replay: accumulate lbwd into shared ----
        // g is bwd at pos base+31 (suffix scan handles cross-segment boundary)
        m0 = g0; m1 = g1;
        {
            int idx = swz(base + CH_SEG - 1);
            sb0[idx] += m0; sb1[idx] += m1;
        }
        #pragma unroll
        for (int k = CH_SEG - 2; k >= 0; k--) {   // bwd[base+k] = T_{c[base+k+1]}(m)
            float c = ((w >> (k + 1)) & 1u) ? c1 : c0;
            step_vec(m0, m1, c, a);
            int idx = swz(base + k);
            sb0[idx] += m0; sb1[idx] += m1;
        }
        __syncthreads();

        // ---- 8. vectorized epilogue: exp2 + float4 stores ----
        float4* o0 = (float4*)(out + (size_t)row * 2 * CH_L);
        float4* o1 = (float4*)(out + (size_t)row * 2 * CH_L + CH_L);
        #pragma unroll
        for (int t4 = tid * 4; t4 < CH_L; t4 += CH_T * 4) {
            float4 u0, u1;
            u0.x = ex2(sb0[swz(t4 + 0)]);
            u0.y = ex2(sb0[swz(t4 + 1)]);
            u0.z = ex2(sb0[swz(t4 + 2)]);
            u0.w = ex2(sb0[swz(t4 + 3)]);
            u1.x = ex2(sb1[swz(t4 + 0)]);
            u1.y = ex2(sb1[swz(t4 + 1)]);
            u1.z = ex2(sb1[swz(t4 + 2)]);
            u1.w = ex2(sb1[swz(t4 + 3)]);
            o0[t4 >> 2] = u0;
            o1[t4 >> 2] = u1;
        }
        __syncthreads();   // sb / sbits / sm reuse barrier before next row
    }
}

extern "C" void kernel_launch(void* const* d_in, const int* in_sizes, int n_in,
                              void* d_out, int out_size) {
    const float* jp  = (const float*)d_in[0];
    const float* bp  = (const float*)d_in[1];
    const int*   obs = (const int*)  d_in[2];
    float*       out = (float*)d_out;

    int B = in_sizes[2] / CH_L;
    int grid = 148 * 5;          // match 5-block/SM residency (96-reg class kernel)
    if (grid > B) grid = B;
    chain_bp_kernel<<<grid, CH_T>>>(jp, bp, obs, out, B);
}